// round 4
// baseline (speedup 1.0000x reference)
#include <cuda_runtime.h>
#include <cuda_bf16.h>
#include <stdint.h>

#define N_MEM   100000
#define NPAD    100096
#define DIM     1024
#define BQ      256
#define KOUT    16
#define NT      782          // n-tiles of 128 rows
#define KC      16           // k-chunks of 64
#define CCAP    1024
#define CSEL    128

#define STG     32768        // per-stage: A 16KB + B 16KB
#define SM_RS   (2 * STG)    // 65536
#define GEMM_SMEM (SM_RS + 1024)

// ---------------- static device scratch (no allocation) ----------------
__device__ __align__(16) float          g_sims[(size_t)BQ * NPAD];  // ~102.5 MB
__device__ __align__(16) __nv_bfloat16  g_qbf[BQ * DIM];
__device__ float g_qn[BQ];
__device__ float g_mn[NPAD];

// ---------------- helpers ----------------
__device__ __forceinline__ unsigned smem_u32(const void* p) {
    unsigned a;
    asm("{ .reg .u64 t; cvta.to.shared.u64 t, %1; cvt.u32.u64 %0, t; }" : "=r"(a) : "l"(p));
    return a;
}
static __device__ __forceinline__ unsigned sw128(unsigned off) { return off ^ ((off >> 3) & 0x70u); }
static __device__ __forceinline__ unsigned fkey(float f) {
    unsigned u = __float_as_uint(f);
    return (u & 0x80000000u) ? ~u : (u | 0x80000000u);
}
__device__ __forceinline__ void cp_async16(unsigned dst, const void* src) {
    asm volatile("cp.async.cg.shared.global [%0], [%1], 16;" :: "r"(dst), "l"(src) : "memory");
}
__device__ __forceinline__ void ldm_x4(unsigned* r, unsigned addr) {
    asm volatile("ldmatrix.sync.aligned.m8n8.x4.shared.b16 {%0,%1,%2,%3}, [%4];"
                 : "=r"(r[0]), "=r"(r[1]), "=r"(r[2]), "=r"(r[3]) : "r"(addr));
}
__device__ __forceinline__ void mma16816(float* c, const unsigned* a, unsigned b0, unsigned b1) {
    asm volatile("mma.sync.aligned.m16n8k16.row.col.f32.bf16.bf16.f32 "
                 "{%0,%1,%2,%3}, {%4,%5,%6,%7}, {%8,%9}, {%0,%1,%2,%3};"
                 : "+f"(c[0]), "+f"(c[1]), "+f"(c[2]), "+f"(c[3])
                 : "r"(a[0]), "r"(a[1]), "r"(a[2]), "r"(a[3]), "r"(b0), "r"(b1));
}

// ================= K1: query fp32 -> bf16 + exact qn =================
__global__ void __launch_bounds__(128) convq_kernel(const float* __restrict__ q) {
    const int row = blockIdx.x, t = threadIdx.x;
    const float4* s4 = reinterpret_cast<const float4*>(q + (size_t)row * DIM);
    float4 a = s4[2 * t], b = s4[2 * t + 1];
    uint4 o; __nv_bfloat162 h;
    h = __floats2bfloat162_rn(a.x, a.y); o.x = *(unsigned*)&h;
    h = __floats2bfloat162_rn(a.z, a.w); o.y = *(unsigned*)&h;
    h = __floats2bfloat162_rn(b.x, b.y); o.z = *(unsigned*)&h;
    h = __floats2bfloat162_rn(b.z, b.w); o.w = *(unsigned*)&h;
    reinterpret_cast<uint4*>(g_qbf)[(size_t)row * 128 + t] = o;

    float p = a.x*a.x + a.y*a.y + a.z*a.z + a.w*a.w
            + b.x*b.x + b.y*b.y + b.z*b.z + b.w*b.w;
#pragma unroll
    for (int off = 16; off; off >>= 1) p += __shfl_down_sync(0xFFFFFFFFu, p, off);
    __shared__ float wp[4];
    if ((t & 31) == 0) wp[t >> 5] = p;
    __syncthreads();
    if (t == 0) g_qn[row] = sqrtf(wp[0] + wp[1] + wp[2] + wp[3]);
}

// ================= K2: fused convert + HMMA GEMM + scaled-sims epilogue =================
// CTA: 128 queries x 128 memory rows x K=1024. grid = 2*NT, pairs share B via L2.
__global__ void __launch_bounds__(256, 1) gemm_kernel(const float* __restrict__ mem) {
    extern __shared__ char smem[];
    const unsigned sb = smem_u32(smem);
    float* rs = reinterpret_cast<float*>(smem + SM_RS);

    const int tid  = threadIdx.x;
    const int bx   = blockIdx.x;
    const int mi   = bx & 1;
    const int n0   = (bx >> 1) * 128;
    const int lane = tid & 31;
    const int w    = tid >> 5;
    const int wm   = w & 1;        // 2 m-blocks of 64
    const int wn   = w >> 1;       // 4 n-blocks of 32

    const int brow = tid >> 4;     // 0..15 (B-load row base)
    const int bl16 = tid & 15;

    float acc[4][4][4];
#pragma unroll
    for (int a = 0; a < 4; a++)
#pragma unroll
        for (int b = 0; b < 4; b++)
#pragma unroll
            for (int c = 0; c < 4; c++) acc[a][b][c] = 0.f;
    float acc8[8] = {0.f,0.f,0.f,0.f,0.f,0.f,0.f,0.f};

    // ---- A async-copy of chunk kc into stage ----
    auto a_async = [&](int kc, int stage) {
#pragma unroll
        for (int p = 0; p < 4; p++) {
            int idx = p * 256 + tid;
            int row = idx >> 3, c8 = idx & 7;
            const __nv_bfloat16* src = g_qbf + (size_t)(mi * 128 + row) * DIM + kc * 64 + c8 * 8;
            cp_async16(sb + stage * STG + sw128((unsigned)(row * 128 + c8 * 16)), src);
        }
        asm volatile("cp.async.commit_group;" ::: "memory");
    };
    // ---- B global load of chunk kc into regs ----
    auto b_load = [&](int kc, float4* bst) {
#pragma unroll
        for (int j = 0; j < 8; j++) {
            int gr = n0 + brow + 16 * j;
            float4 v = make_float4(0.f, 0.f, 0.f, 0.f);
            if (gr < N_MEM)
                v = *reinterpret_cast<const float4*>(mem + (size_t)gr * DIM + kc * 64 + bl16 * 4);
            bst[j] = v;
        }
    };
    // ---- B convert + STS into stage, accumulate sumsq ----
    auto b_sts = [&](const float4* bst, int stage) {
#pragma unroll
        for (int j = 0; j < 8; j++) {
            float4 v = bst[j];
            acc8[j] += v.x*v.x + v.y*v.y + v.z*v.z + v.w*v.w;
            int row = brow + 16 * j;
            __nv_bfloat162 h01 = __floats2bfloat162_rn(v.x, v.y);
            __nv_bfloat162 h23 = __floats2bfloat162_rn(v.z, v.w);
            uint2 pk = make_uint2(*(unsigned*)&h01, *(unsigned*)&h23);
            *reinterpret_cast<uint2*>(smem + stage * STG + 16384 +
                                      sw128((unsigned)(row * 128 + bl16 * 8))) = pk;
        }
    };

    // ---- prologue: chunk 0 ----
    a_async(0, 0);
    { float4 b0[8]; b_load(0, b0); b_sts(b0, 0); }
    asm volatile("cp.async.wait_group 0;" ::: "memory");
    __syncthreads();

    for (int kc = 0; kc < KC; kc++) {
        const int buf = kc & 1, nxt = buf ^ 1;
        float4 bst[8];
        if (kc + 1 < KC) { a_async(kc + 1, nxt); b_load(kc + 1, bst); }

        const unsigned sA = sb + buf * STG;
        const unsigned sB = sA + 16384;
#pragma unroll
        for (int ks = 0; ks < 4; ks++) {
            unsigned af[4][4], bf[2][4];
#pragma unroll
            for (int mt = 0; mt < 4; mt++)
                ldm_x4(af[mt], sA + sw128((unsigned)((wm*64 + mt*16 + (lane & 15)) * 128
                                                     + ks*32 + ((lane >> 4) << 4))));
#pragma unroll
            for (int nb = 0; nb < 2; nb++)
                ldm_x4(bf[nb], sB + sw128((unsigned)((wn*32 + nb*16 + ((lane >> 4) << 3) + (lane & 7)) * 128
                                                     + ks*32 + (((lane >> 3) & 1) << 4))));
#pragma unroll
            for (int mt = 0; mt < 4; mt++)
#pragma unroll
                for (int nt = 0; nt < 4; nt++)
                    mma16816(acc[mt][nt], af[mt], bf[nt >> 1][(nt & 1) * 2], bf[nt >> 1][(nt & 1) * 2 + 1]);
        }
        if (kc + 1 < KC) b_sts(bst, nxt);
        asm volatile("cp.async.wait_group 0;" ::: "memory");
        __syncthreads();
    }

    // ---- row norms: reduce sumsq across the 16 lanes of each row ----
#pragma unroll
    for (int j = 0; j < 8; j++) {
        float s = acc8[j];
        s += __shfl_xor_sync(0xFFFFFFFFu, s, 8, 16);
        s += __shfl_xor_sync(0xFFFFFFFFu, s, 4, 16);
        s += __shfl_xor_sync(0xFFFFFFFFu, s, 2, 16);
        s += __shfl_xor_sync(0xFFFFFFFFu, s, 1, 16);
        if (bl16 == 0) rs[brow + 16 * j] = s;
    }
    __syncthreads();
    if (tid < 128) {
        float ss = rs[tid];
        if (mi == 0 && n0 + tid < N_MEM) g_mn[n0 + tid] = sqrtf(ss);
        rs[tid] = (ss > 0.f) ? rsqrtf(ss) : 0.f;
    }
    __syncthreads();

    // ---- epilogue: scaled ranking scores ----
#pragma unroll
    for (int mt = 0; mt < 4; mt++) {
        int q = mi * 128 + wm * 64 + mt * 16 + (lane >> 2);
#pragma unroll
        for (int nt = 0; nt < 4; nt++) {
            int col = wn * 32 + nt * 8 + ((lane & 3) << 1);
            float r0 = rs[col], r1 = rs[col + 1];
            float2 v0 = make_float2(acc[mt][nt][0] * r0, acc[mt][nt][1] * r1);
            float2 v1 = make_float2(acc[mt][nt][2] * r0, acc[mt][nt][3] * r1);
            *reinterpret_cast<float2*>(g_sims + (size_t)q       * NPAD + n0 + col) = v0;
            *reinterpret_cast<float2*>(g_sims + (size_t)(q + 8) * NPAD + n0 + col) = v1;
        }
    }
}

// ================= K3: radix-threshold candidates + exact fp32 rescore + top-16 =================
__global__ void __launch_bounds__(1024) select_kernel(
    const float* __restrict__ query, const float* __restrict__ mem, float* __restrict__ out) {
    __shared__ unsigned hist[4096];
    __shared__ int s_cnt, s_bth;
    __shared__ int cand[CCAP];
    __shared__ float simv[CCAP];
    __shared__ unsigned long long comp[CCAP];
    __shared__ __align__(16) float qs[1024];

    const int q = blockIdx.x;
    const int tid = threadIdx.x;
    const int lane = tid & 31;
    const float* srow = g_sims + (size_t)q * NPAD;

    qs[tid] = query[(size_t)q * DIM + tid];
#pragma unroll
    for (int i = tid; i < 4096; i += 1024) hist[i] = 0;
    if (tid == 0) s_cnt = 0;
    __syncthreads();

    // pass 1: 12-bit histogram of order-preserving keys (warp-aggregated atomics)
    for (int n = tid; n < 100352; n += 1024) {
        unsigned b = 0;
        if (n < N_MEM) b = fkey(srow[n]) >> 20;
        unsigned m = __match_any_sync(0xFFFFFFFFu, b);
        if ((m & ((1u << lane) - 1u)) == 0) atomicAdd(&hist[b], __popc(m));
    }
    __syncthreads();
    if (tid == 0) {
        unsigned cum = 0; int b = 4095;               // FIX: full key range
        for (; b > 0; b--) { cum += hist[b]; if (cum >= CSEL) break; }
        s_bth = b;
    }
    __syncthreads();
    const unsigned bth = (unsigned)s_bth;

    // pass 2: gather candidate superset
    for (int n = tid; n < N_MEM; n += 1024) {
        if ((fkey(srow[n]) >> 20) >= bth) {
            int p = atomicAdd(&s_cnt, 1);
            if (p < CCAP) cand[p] = n;
        }
    }
    __syncthreads();
    const int C = min(s_cnt, CCAP);
    const float qn = g_qn[q];

    // exact fp32 rescore: one warp per candidate
    const int w = tid >> 5;
    for (int c = w; c < C; c += 32) {
        const int idx = cand[c];
        const float4* m4 = reinterpret_cast<const float4*>(mem + (size_t)idx * DIM);
        const float4* q4 = reinterpret_cast<const float4*>(qs);
        float a = 0.f;
#pragma unroll
        for (int j = 0; j < 8; j++) {
            float4 mv = m4[j * 32 + lane];
            float4 qv = q4[j * 32 + lane];
            a = fmaf(mv.x, qv.x, a); a = fmaf(mv.y, qv.y, a);
            a = fmaf(mv.z, qv.z, a); a = fmaf(mv.w, qv.w, a);
        }
#pragma unroll
        for (int off = 16; off; off >>= 1) a += __shfl_down_sync(0xFFFFFFFFu, a, off);
        if (lane == 0) {
            float sim = a / fmaxf(qn * g_mn[idx], 1e-8f);
            simv[c] = sim;
            comp[c] = ((unsigned long long)fkey(sim) << 32) | (unsigned)(~(unsigned)idx);
        }
    }
    __syncthreads();

    // exact rank (ties -> lower index, matching lax.top_k)
    for (int i = tid; i < C; i += 1024) {
        const unsigned long long ci = comp[i];
        int r = 0;
        for (int j = 0; j < C; j++) r += (comp[j] > ci);
        if (r < KOUT) {
            out[q * KOUT + r] = simv[i];
            out[BQ * KOUT + q * KOUT + r] = (float)cand[i];
        }
    }
}

extern "C" void kernel_launch(void* const* d_in, const int* in_sizes, int n_in,
                              void* d_out, int out_size) {
    (void)in_sizes; (void)n_in; (void)out_size;
    const float* query = (const float*)d_in[0];
    const float* mem   = (const float*)d_in[1];
    cudaFuncSetAttribute(gemm_kernel, cudaFuncAttributeMaxDynamicSharedMemorySize, GEMM_SMEM);
    convq_kernel<<<BQ, 128>>>(query);
    gemm_kernel<<<2 * NT, 256, GEMM_SMEM>>>(mem);
    select_kernel<<<BQ, 1024>>>(query, mem, (float*)d_out);
}

// round 5
// speedup vs baseline: 1.0469x; 1.0469x over previous
#include <cuda_runtime.h>
#include <cuda.h>
#include <cuda_bf16.h>
#include <stdint.h>

#define N_MEM   100000
#define NPAD    100096
#define DIM     1024
#define BQ      256
#define KOUT    16
#define NT      782          // n-tiles of 128 rows
#define KC      16           // k-chunks of 64
#define CCAP    1024
#define CSEL    128

// ---- gemm smem layout (bytes) ----
#define OFF_A(s)   ((s) * 32768)            // 3 x 32KB  A bf16 SW128 (256x64)
#define OFF_BF(s)  (98304 + (s) * 32768)    // 3 x 32KB  B fp32 staging (128x64)
#define OFF_BMMA   196608                   // 16KB      B bf16 SW128 (128x64)
#define OFF_RS     212992                   // 512B      row sumsq
#define OFF_MBAR   213504                   // 3 mbarriers
#define GEMM_SMEM  213568

// ---------------- static device scratch (no allocation) ----------------
__device__ __align__(16) float          g_sims[(size_t)BQ * NPAD];  // ~102.5 MB
__device__ __align__(16) __nv_bfloat16  g_qbf[BQ * DIM];
__device__ float g_qn[BQ];
__device__ float g_mn[NPAD];

// ---------------- helpers ----------------
__device__ __forceinline__ unsigned smem_u32(const void* p) {
    unsigned a;
    asm("{ .reg .u64 t; cvta.to.shared.u64 t, %1; cvt.u32.u64 %0, t; }" : "=r"(a) : "l"(p));
    return a;
}
static __device__ __forceinline__ unsigned sw128(unsigned off) { return off ^ ((off >> 3) & 0x70u); }
static __device__ __forceinline__ unsigned fkey(float f) {
    unsigned u = __float_as_uint(f);
    return (u & 0x80000000u) ? ~u : (u | 0x80000000u);
}
__device__ __forceinline__ void ldm_x4(unsigned* r, unsigned addr) {
    asm volatile("ldmatrix.sync.aligned.m8n8.x4.shared.b16 {%0,%1,%2,%3}, [%4];"
                 : "=r"(r[0]), "=r"(r[1]), "=r"(r[2]), "=r"(r[3]) : "r"(addr));
}
__device__ __forceinline__ void mma16816(float* c, const unsigned* a, unsigned b0, unsigned b1) {
    asm volatile("mma.sync.aligned.m16n8k16.row.col.f32.bf16.bf16.f32 "
                 "{%0,%1,%2,%3}, {%4,%5,%6,%7}, {%8,%9}, {%0,%1,%2,%3};"
                 : "+f"(c[0]), "+f"(c[1]), "+f"(c[2]), "+f"(c[3])
                 : "r"(a[0]), "r"(a[1]), "r"(a[2]), "r"(a[3]), "r"(b0), "r"(b1));
}
__device__ __forceinline__ void mbar_init(unsigned mbar, unsigned cnt) {
    asm volatile("mbarrier.init.shared.b64 [%0], %1;" :: "r"(mbar), "r"(cnt) : "memory");
}
__device__ __forceinline__ void mbar_expect_tx(unsigned mbar, unsigned bytes) {
    asm volatile("mbarrier.arrive.expect_tx.shared.b64 _, [%0], %1;"
                 :: "r"(mbar), "r"(bytes) : "memory");
}
__device__ __forceinline__ void mbar_wait(unsigned mbar, unsigned parity) {
    asm volatile(
        "{\n\t.reg .pred P;\n\t"
        "WL_%=:\n\t"
        "mbarrier.try_wait.parity.acquire.cta.shared::cta.b64 P, [%0], %1, 0x989680;\n\t"
        "@P bra.uni WD_%=;\n\t"
        "bra.uni WL_%=;\n\t"
        "WD_%=:\n\t}"
        :: "r"(mbar), "r"(parity) : "memory");
}
__device__ __forceinline__ void tma2d(unsigned dst, const void* map, int x, int y, unsigned mbar) {
    asm volatile("cp.async.bulk.tensor.2d.shared::cta.global.tile.mbarrier::complete_tx::bytes "
                 "[%0], [%1, {%2, %3}], [%4];"
                 :: "r"(dst), "l"(map), "r"(x), "r"(y), "r"(mbar) : "memory");
}

// ================= K1: query fp32 -> bf16 + exact qn =================
__global__ void __launch_bounds__(128) convq_kernel(const float* __restrict__ q) {
    const int row = blockIdx.x, t = threadIdx.x;
    const float4* s4 = reinterpret_cast<const float4*>(q + (size_t)row * DIM);
    float4 a = s4[2 * t], b = s4[2 * t + 1];
    uint4 o; __nv_bfloat162 h;
    h = __floats2bfloat162_rn(a.x, a.y); o.x = *(unsigned*)&h;
    h = __floats2bfloat162_rn(a.z, a.w); o.y = *(unsigned*)&h;
    h = __floats2bfloat162_rn(b.x, b.y); o.z = *(unsigned*)&h;
    h = __floats2bfloat162_rn(b.z, b.w); o.w = *(unsigned*)&h;
    reinterpret_cast<uint4*>(g_qbf)[(size_t)row * 128 + t] = o;

    float p = a.x*a.x + a.y*a.y + a.z*a.z + a.w*a.w
            + b.x*b.x + b.y*b.y + b.z*b.z + b.w*b.w;
#pragma unroll
    for (int off = 16; off; off >>= 1) p += __shfl_down_sync(0xFFFFFFFFu, p, off);
    __shared__ float wp[4];
    if ((t & 31) == 0) wp[t >> 5] = p;
    __syncthreads();
    if (t == 0) g_qn[row] = sqrtf(wp[0] + wp[1] + wp[2] + wp[3]);
}

// ================= K2: TMA-fed HMMA GEMM, 256q x 128n per CTA =================
__global__ void __launch_bounds__(512, 1) gemm_kernel(
    const __grid_constant__ CUtensorMap tmA,
    const __grid_constant__ CUtensorMap tmB) {
    extern __shared__ char smem[];
    const unsigned sb = smem_u32(smem);
    float* rs = reinterpret_cast<float*>(smem + OFF_RS);

    const int tid  = threadIdx.x;
    const int n0   = blockIdx.x * 128;
    const int lane = tid & 31;
    const int w    = tid >> 5;
    const int wm   = w & 3;        // 4 m-blocks of 64 (over 256 queries)
    const int wn   = w >> 2;       // 4 n-blocks of 32

    const int r8 = tid >> 3;       // 0..63  (B convert: row base)
    const int c8 = tid & 7;        // 0..7   (B convert: 8-float column chunk)

    float acc[4][4][4];
#pragma unroll
    for (int a = 0; a < 4; a++)
#pragma unroll
        for (int b = 0; b < 4; b++)
#pragma unroll
            for (int c = 0; c < 4; c++) acc[a][b][c] = 0.f;
    float acc2[2] = {0.f, 0.f};

    if (tid == 0) {
        mbar_init(sb + OFF_MBAR + 0, 1);
        mbar_init(sb + OFF_MBAR + 8, 1);
        mbar_init(sb + OFF_MBAR + 16, 1);
    }
    __syncthreads();

    // prologue: stage chunks 0 and 1
    if (tid == 0) {
#pragma unroll
        for (int kc = 0; kc < 2; kc++) {
            mbar_expect_tx(sb + OFF_MBAR + 8 * kc, 65536);
            tma2d(sb + OFF_A(kc),  &tmA, kc * 64, 0,  sb + OFF_MBAR + 8 * kc);
            tma2d(sb + OFF_BF(kc), &tmB, kc * 64, n0, sb + OFF_MBAR + 8 * kc);
        }
    }

    for (int kc = 0; kc < KC; kc++) {
        const int s = kc % 3;
        if (kc + 2 < KC && tid == 0) {
            const int s2 = (kc + 2) % 3;
            mbar_expect_tx(sb + OFF_MBAR + 8 * s2, 65536);
            tma2d(sb + OFF_A(s2),  &tmA, (kc + 2) * 64, 0,  sb + OFF_MBAR + 8 * s2);
            tma2d(sb + OFF_BF(s2), &tmB, (kc + 2) * 64, n0, sb + OFF_MBAR + 8 * s2);
        }
        mbar_wait(sb + OFF_MBAR + 8 * s, (kc / 3) & 1);

        // ---- convert B fp32 -> bf16 (SW128) + exact sumsq ----
#pragma unroll
        for (int j = 0; j < 2; j++) {
            const int row = r8 + 64 * j;
            const char* src = smem + OFF_BF(s) + row * 256 + c8 * 32;
            float4 v0 = *reinterpret_cast<const float4*>(src);
            float4 v1 = *reinterpret_cast<const float4*>(src + 16);
            acc2[j] += v0.x*v0.x + v0.y*v0.y + v0.z*v0.z + v0.w*v0.w
                     + v1.x*v1.x + v1.y*v1.y + v1.z*v1.z + v1.w*v1.w;
            uint4 pk; __nv_bfloat162 h;
            h = __floats2bfloat162_rn(v0.x, v0.y); pk.x = *(unsigned*)&h;
            h = __floats2bfloat162_rn(v0.z, v0.w); pk.y = *(unsigned*)&h;
            h = __floats2bfloat162_rn(v1.x, v1.y); pk.z = *(unsigned*)&h;
            h = __floats2bfloat162_rn(v1.z, v1.w); pk.w = *(unsigned*)&h;
            *reinterpret_cast<uint4*>(smem + OFF_BMMA + sw128((unsigned)(row * 128 + c8 * 16))) = pk;
        }
        __syncthreads();

        // ---- MMAs: 4 k-steps of 16 ----
        const unsigned sA = sb + OFF_A(s);
        const unsigned sB = sb + OFF_BMMA;
#pragma unroll
        for (int ks = 0; ks < 4; ks++) {
            unsigned af[4][4], bf[2][4];
#pragma unroll
            for (int mt = 0; mt < 4; mt++)
                ldm_x4(af[mt], sA + sw128((unsigned)((wm*64 + mt*16 + (lane & 15)) * 128
                                                     + ks*32 + ((lane >> 4) << 4))));
#pragma unroll
            for (int nb = 0; nb < 2; nb++)
                ldm_x4(bf[nb], sB + sw128((unsigned)((wn*32 + nb*16 + ((lane >> 4) << 3) + (lane & 7)) * 128
                                                     + ks*32 + (((lane >> 3) & 1) << 4))));
#pragma unroll
            for (int mt = 0; mt < 4; mt++)
#pragma unroll
                for (int nt = 0; nt < 4; nt++)
                    mma16816(acc[mt][nt], af[mt], bf[nt >> 1][(nt & 1) * 2], bf[nt >> 1][(nt & 1) * 2 + 1]);
        }
        __syncthreads();
    }

    // ---- row norms: reduce sumsq over the 8 lanes of each row ----
#pragma unroll
    for (int j = 0; j < 2; j++) {
        float ssum = acc2[j];
        ssum += __shfl_xor_sync(0xFFFFFFFFu, ssum, 4, 8);
        ssum += __shfl_xor_sync(0xFFFFFFFFu, ssum, 2, 8);
        ssum += __shfl_xor_sync(0xFFFFFFFFu, ssum, 1, 8);
        if (c8 == 0) rs[r8 + 64 * j] = ssum;
    }
    __syncthreads();
    if (tid < 128) {
        float ss = rs[tid];
        if (n0 + tid < N_MEM) g_mn[n0 + tid] = sqrtf(ss);
        rs[tid] = (ss > 0.f) ? rsqrtf(ss) : 0.f;
    }
    __syncthreads();

    // ---- epilogue: scaled ranking scores ----
#pragma unroll
    for (int mt = 0; mt < 4; mt++) {
        int q = wm * 64 + mt * 16 + (lane >> 2);
#pragma unroll
        for (int nt = 0; nt < 4; nt++) {
            int col = wn * 32 + nt * 8 + ((lane & 3) << 1);
            float r0 = rs[col], r1 = rs[col + 1];
            float2 v0 = make_float2(acc[mt][nt][0] * r0, acc[mt][nt][1] * r1);
            float2 v1 = make_float2(acc[mt][nt][2] * r0, acc[mt][nt][3] * r1);
            *reinterpret_cast<float2*>(g_sims + (size_t)q       * NPAD + n0 + col) = v0;
            *reinterpret_cast<float2*>(g_sims + (size_t)(q + 8) * NPAD + n0 + col) = v1;
        }
    }
}

// ================= K3: radix-threshold candidates + exact fp32 rescore + top-16 =================
__global__ void __launch_bounds__(1024) select_kernel(
    const float* __restrict__ query, const float* __restrict__ mem, float* __restrict__ out) {
    __shared__ unsigned hist[4096];
    __shared__ int s_cnt, s_bth;
    __shared__ int cand[CCAP];
    __shared__ float simv[CCAP];
    __shared__ unsigned long long comp[CCAP];
    __shared__ __align__(16) float qs[1024];

    const int q = blockIdx.x;
    const int tid = threadIdx.x;
    const int lane = tid & 31;
    const float* srow = g_sims + (size_t)q * NPAD;

    qs[tid] = query[(size_t)q * DIM + tid];
#pragma unroll
    for (int i = tid; i < 4096; i += 1024) hist[i] = 0;
    if (tid == 0) s_cnt = 0;
    __syncthreads();

    // pass 1: 12-bit histogram of order-preserving keys (warp-aggregated atomics)
    for (int n = tid; n < 100352; n += 1024) {
        unsigned b = 0;
        if (n < N_MEM) b = fkey(srow[n]) >> 20;
        unsigned m = __match_any_sync(0xFFFFFFFFu, b);
        if ((m & ((1u << lane) - 1u)) == 0) atomicAdd(&hist[b], __popc(m));
    }
    __syncthreads();
    if (tid == 0) {
        unsigned cum = 0; int b = 4095;
        for (; b > 0; b--) { cum += hist[b]; if (cum >= CSEL) break; }
        s_bth = b;
    }
    __syncthreads();
    const unsigned bth = (unsigned)s_bth;

    // pass 2: gather candidate superset
    for (int n = tid; n < N_MEM; n += 1024) {
        if ((fkey(srow[n]) >> 20) >= bth) {
            int p = atomicAdd(&s_cnt, 1);
            if (p < CCAP) cand[p] = n;
        }
    }
    __syncthreads();
    const int C = min(s_cnt, CCAP);
    const float qn = g_qn[q];

    // exact fp32 rescore: one warp per candidate
    const int w = tid >> 5;
    for (int c = w; c < C; c += 32) {
        const int idx = cand[c];
        const float4* m4 = reinterpret_cast<const float4*>(mem + (size_t)idx * DIM);
        const float4* q4 = reinterpret_cast<const float4*>(qs);
        float a = 0.f;
#pragma unroll
        for (int j = 0; j < 8; j++) {
            float4 mv = m4[j * 32 + lane];
            float4 qv = q4[j * 32 + lane];
            a = fmaf(mv.x, qv.x, a); a = fmaf(mv.y, qv.y, a);
            a = fmaf(mv.z, qv.z, a); a = fmaf(mv.w, qv.w, a);
        }
#pragma unroll
        for (int off = 16; off; off >>= 1) a += __shfl_down_sync(0xFFFFFFFFu, a, off);
        if (lane == 0) {
            float sim = a / fmaxf(qn * g_mn[idx], 1e-8f);
            simv[c] = sim;
            comp[c] = ((unsigned long long)fkey(sim) << 32) | (unsigned)(~(unsigned)idx);
        }
    }
    __syncthreads();

    // exact rank (ties -> lower index, matching lax.top_k)
    for (int i = tid; i < C; i += 1024) {
        const unsigned long long ci = comp[i];
        int r = 0;
        for (int j = 0; j < C; j++) r += (comp[j] > ci);
        if (r < KOUT) {
            out[q * KOUT + r] = simv[i];
            out[BQ * KOUT + q * KOUT + r] = (float)cand[i];
        }
    }
}

// ---------------- host: tensor-map construction (no -lcuda link dep) ----------------
typedef CUresult (*PFN_tmenc)(CUtensorMap*, CUtensorMapDataType, cuuint32_t, void*,
                              const cuuint64_t*, const cuuint64_t*, const cuuint32_t*,
                              const cuuint32_t*, CUtensorMapInterleave, CUtensorMapSwizzle,
                              CUtensorMapL2promotion, CUtensorMapFloatOOBfill);

extern "C" void kernel_launch(void* const* d_in, const int* in_sizes, int n_in,
                              void* d_out, int out_size) {
    (void)in_sizes; (void)n_in; (void)out_size;
    const float* query = (const float*)d_in[0];
    const float* mem   = (const float*)d_in[1];

    PFN_tmenc tmenc = nullptr;
    cudaDriverEntryPointQueryResult qres;
    cudaGetDriverEntryPoint("cuTensorMapEncodeTiled", (void**)&tmenc, cudaEnableDefault, &qres);

    void* qbf_ptr = nullptr;
    cudaGetSymbolAddress(&qbf_ptr, g_qbf);

    CUtensorMap tmA, tmB;
    {
        cuuint64_t dims[2]    = {DIM, BQ};
        cuuint64_t strides[1] = {DIM * 2};
        cuuint32_t box[2]     = {64, 256};
        cuuint32_t estr[2]    = {1, 1};
        tmenc(&tmA, CU_TENSOR_MAP_DATA_TYPE_BFLOAT16, 2, qbf_ptr, dims, strides, box, estr,
              CU_TENSOR_MAP_INTERLEAVE_NONE, CU_TENSOR_MAP_SWIZZLE_128B,
              CU_TENSOR_MAP_L2_PROMOTION_L2_128B, CU_TENSOR_MAP_FLOAT_OOB_FILL_NONE);
    }
    {
        cuuint64_t dims[2]    = {DIM, N_MEM};
        cuuint64_t strides[1] = {DIM * 4};
        cuuint32_t box[2]     = {64, 128};
        cuuint32_t estr[2]    = {1, 1};
        tmenc(&tmB, CU_TENSOR_MAP_DATA_TYPE_FLOAT32, 2, (void*)mem, dims, strides, box, estr,
              CU_TENSOR_MAP_INTERLEAVE_NONE, CU_TENSOR_MAP_SWIZZLE_NONE,
              CU_TENSOR_MAP_L2_PROMOTION_L2_128B, CU_TENSOR_MAP_FLOAT_OOB_FILL_NONE);
    }

    cudaFuncSetAttribute(gemm_kernel, cudaFuncAttributeMaxDynamicSharedMemorySize, GEMM_SMEM);
    convq_kernel<<<BQ, 128>>>(query);
    gemm_kernel<<<NT, 512, GEMM_SMEM>>>(tmA, tmB);
    select_kernel<<<BQ, 1024>>>(query, mem, (float*)d_out);
}